// round 5
// baseline (speedup 1.0000x reference)
#include <cuda_runtime.h>

#define CN 100000
#define CE 1600000

// ---------------- device scratch (static, no allocation) ----------------
__device__ int   g_deg[CN];
__device__ int   g_incl[CN];
__device__ int   g_bsum[128];
__device__ int   g_rowptr[CN + 1];
__device__ int   g_wp[CN];
__device__ int   g_col[CE];
__device__ float g_mean1[(size_t)CN * 64];
__device__ float g_h[(size_t)CN * 128];
__device__ float g_mean2[(size_t)CN * 128];
__device__ float g_W1t[128 * 128];   // [k][o] concat(W1_l, W1_r) transposed
__device__ float g_W2t[256 * 64];    // [k][o] concat(W2_l, W2_r) transposed

// ---------------- CSR construction ----------------
__global__ void k_zero_deg() {
    int i = blockIdx.x * blockDim.x + threadIdx.x;
    if (i < CN) g_deg[i] = 0;
}

__global__ void k_count(const int* __restrict__ ei) {
    int e = blockIdx.x * blockDim.x + threadIdx.x;
    if (e < CE) atomicAdd(&g_deg[ei[CE + e]], 1);
}

__global__ void k_scan_local() {
    __shared__ int sh[1024];
    int t = threadIdx.x;
    int i = blockIdx.x * 1024 + t;
    int v = (i < CN) ? g_deg[i] : 0;
    sh[t] = v;
    __syncthreads();
    for (int off = 1; off < 1024; off <<= 1) {
        int cur = sh[t];
        int add = (t >= off) ? sh[t - off] : 0;
        __syncthreads();
        sh[t] = cur + add;
        __syncthreads();
    }
    if (i < CN) g_incl[i] = sh[t];
    if (t == 1023) g_bsum[blockIdx.x] = sh[1023];
}

__global__ void k_scan_bsum(int nb) {
    if (threadIdx.x == 0) {
        int acc = 0;
        for (int i = 0; i < nb; i++) { int v = g_bsum[i]; g_bsum[i] = acc; acc += v; }
    }
}

__global__ void k_finalize() {
    int i = blockIdx.x * blockDim.x + threadIdx.x;
    if (i < CN) {
        int r = g_incl[i] + g_bsum[i >> 10];
        g_rowptr[i + 1] = r;
        g_wp[i] = r - g_deg[i];
        if (i == 0) g_rowptr[0] = 0;
    }
}

__global__ void k_fill(const int* __restrict__ ei) {
    int e = blockIdx.x * blockDim.x + threadIdx.x;
    if (e < CE) {
        int s = ei[e];
        int d = ei[CE + e];
        int p = atomicAdd(&g_wp[d], 1);
        g_col[p] = s;
    }
}

// ---------------- weight transpose: [o][k] -> concat [k][o] ----------------
__global__ void k_wt1(const float* __restrict__ Wl, const float* __restrict__ Wr) {
    int idx = blockIdx.x * blockDim.x + threadIdx.x;
    if (idx < 128 * 128) {
        int k = idx >> 7, o = idx & 127;
        g_W1t[idx] = (k < 64) ? Wl[o * 64 + k] : Wr[o * 64 + (k - 64)];
    }
}
__global__ void k_wt2(const float* __restrict__ Wl, const float* __restrict__ Wr) {
    int idx = blockIdx.x * blockDim.x + threadIdx.x;
    if (idx < 256 * 64) {
        int k = idx >> 6, o = idx & 63;
        g_W2t[idx] = (k < 128) ? Wl[o * 128 + k] : Wr[o * 128 + (k - 128)];
    }
}

// ---------------- mean aggregation (warp per node, gather, no atomics) ----------------
// 2-way unrolled: independent column + feature loads raise per-warp MLP.
__global__ void k_agg64(const float* __restrict__ feat, float* __restrict__ outm) {
    int w = (blockIdx.x * blockDim.x + threadIdx.x) >> 5;
    int lane = threadIdx.x & 31;
    if (w >= CN) return;
    int s = g_rowptr[w], e = g_rowptr[w + 1];
    float ax = 0.f, ay = 0.f, bx = 0.f, by = 0.f;
    const float2* base = reinterpret_cast<const float2*>(feat);
    int j = s;
    for (; j + 1 < e; j += 2) {
        int c0 = g_col[j];
        int c1 = g_col[j + 1];
        float2 v0 = __ldg(base + (size_t)c0 * 32 + lane);
        float2 v1 = __ldg(base + (size_t)c1 * 32 + lane);
        ax += v0.x; ay += v0.y;
        bx += v1.x; by += v1.y;
    }
    if (j < e) {
        int c0 = g_col[j];
        float2 v0 = __ldg(base + (size_t)c0 * 32 + lane);
        ax += v0.x; ay += v0.y;
    }
    int d = e - s;
    float inv = 1.f / (float)(d > 0 ? d : 1);
    float2 r; r.x = (ax + bx) * inv; r.y = (ay + by) * inv;
    reinterpret_cast<float2*>(outm)[(size_t)w * 32 + lane] = r;
}

__global__ void k_agg128(const float* __restrict__ feat, float* __restrict__ outm) {
    int w = (blockIdx.x * blockDim.x + threadIdx.x) >> 5;
    int lane = threadIdx.x & 31;
    if (w >= CN) return;
    int s = g_rowptr[w], e = g_rowptr[w + 1];
    float ax = 0.f, ay = 0.f, az = 0.f, aw = 0.f;
    float bx = 0.f, by = 0.f, bz = 0.f, bw = 0.f;
    const float4* base = reinterpret_cast<const float4*>(feat);
    int j = s;
    for (; j + 1 < e; j += 2) {
        int c0 = g_col[j];
        int c1 = g_col[j + 1];
        float4 v0 = __ldg(base + (size_t)c0 * 32 + lane);
        float4 v1 = __ldg(base + (size_t)c1 * 32 + lane);
        ax += v0.x; ay += v0.y; az += v0.z; aw += v0.w;
        bx += v1.x; by += v1.y; bz += v1.z; bw += v1.w;
    }
    if (j < e) {
        int c0 = g_col[j];
        float4 v0 = __ldg(base + (size_t)c0 * 32 + lane);
        ax += v0.x; ay += v0.y; az += v0.z; aw += v0.w;
    }
    int d = e - s;
    float inv = 1.f / (float)(d > 0 ? d : 1);
    float4 r;
    r.x = (ax + bx) * inv; r.y = (ay + by) * inv;
    r.z = (az + bz) * inv; r.w = (aw + bw) * inv;
    reinterpret_cast<float4*>(outm)[(size_t)w * 32 + lane] = r;
}

// ---------------- fused concat GEMM: out = [Aa|As] @ Wt + b (+relu) ----------------
// Wt is pre-transposed [K][NOUT] in global. Block: 256 threads, tile 64 rows x NOUT.
template <int K, int NOUT, bool RELU>
__global__ void k_gemm(const float* __restrict__ Aa, const float* __restrict__ Asf,
                       const float* __restrict__ Wt, const float* __restrict__ bias,
                       float* __restrict__ out) {
    constexpr int TM = 64, TMP = 65, KH = K / 2, RN = NOUT / 16;
    extern __shared__ float sh[];
    float* Ash = sh;             // [K][TMP]  (padded -> conflict-free transpose)
    float* Wsh = sh + K * TMP;   // [K][NOUT]
    const int tid = threadIdx.x;
    const int m0 = blockIdx.x * TM;

    for (int idx = tid; idx < K * NOUT; idx += 256) Wsh[idx] = Wt[idx];

    for (int idx = tid; idx < TM * K; idx += 256) {
        int m = idx / K, k = idx - m * K;
        int row = m0 + m;
        float v = 0.f;
        if (row < CN)
            v = (k < KH) ? __ldg(&Aa[(size_t)row * KH + k])
                         : __ldg(&Asf[(size_t)row * KH + (k - KH)]);
        Ash[k * TMP + m] = v;
    }
    __syncthreads();

    const int tm = tid & 15;       // node group: rows tm, tm+16, tm+32, tm+48
    const int to = tid >> 4;       // output group: cols [to*RN, to*RN+RN)
    float acc[4][RN];
#pragma unroll
    for (int i = 0; i < 4; i++)
#pragma unroll
        for (int j = 0; j < RN; j++) acc[i][j] = 0.f;

#pragma unroll 4
    for (int k = 0; k < K; k++) {
        float a[4];
#pragma unroll
        for (int i = 0; i < 4; i++) a[i] = Ash[k * TMP + tm + 16 * i];
        float w[RN];
#pragma unroll
        for (int j = 0; j < RN; j += 4) {
            float4 wv = *reinterpret_cast<const float4*>(&Wsh[k * NOUT + to * RN + j]);
            w[j] = wv.x; w[j + 1] = wv.y; w[j + 2] = wv.z; w[j + 3] = wv.w;
        }
#pragma unroll
        for (int i = 0; i < 4; i++)
#pragma unroll
            for (int j = 0; j < RN; j++) acc[i][j] += a[i] * w[j];
    }

#pragma unroll
    for (int i = 0; i < 4; i++) {
        int row = m0 + tm + 16 * i;
        if (row < CN) {
#pragma unroll
            for (int j = 0; j < RN; j += 4) {
                int o = to * RN + j;
                float4 r;
                r.x = acc[i][j]     + __ldg(&bias[o]);
                r.y = acc[i][j + 1] + __ldg(&bias[o + 1]);
                r.z = acc[i][j + 2] + __ldg(&bias[o + 2]);
                r.w = acc[i][j + 3] + __ldg(&bias[o + 3]);
                if (RELU) {
                    r.x = fmaxf(r.x, 0.f); r.y = fmaxf(r.y, 0.f);
                    r.z = fmaxf(r.z, 0.f); r.w = fmaxf(r.w, 0.f);
                }
                *reinterpret_cast<float4*>(&out[(size_t)row * NOUT + o]) = r;
            }
        }
    }
}

// ---------------- host launch ----------------
extern "C" void kernel_launch(void* const* d_in, const int* in_sizes, int n_in,
                              void* d_out, int out_size) {
    const float* x    = (const float*)d_in[0];
    const int*   ei   = (const int*)d_in[1];
    const float* W1_l = (const float*)d_in[2];
    const float* b1_l = (const float*)d_in[3];
    const float* W1_r = (const float*)d_in[4];
    const float* W2_l = (const float*)d_in[5];
    const float* b2_l = (const float*)d_in[6];
    const float* W2_r = (const float*)d_in[7];
    float* out = (float*)d_out;

    void *p_mean1, *p_h, *p_mean2, *p_w1t, *p_w2t;
    cudaGetSymbolAddress(&p_mean1, g_mean1);
    cudaGetSymbolAddress(&p_h, g_h);
    cudaGetSymbolAddress(&p_mean2, g_mean2);
    cudaGetSymbolAddress(&p_w1t, g_W1t);
    cudaGetSymbolAddress(&p_w2t, g_W2t);

    const size_t sh1 = (size_t)(128 * 65 + 128 * 128) * 4;  // 98816 B
    const size_t sh2 = (size_t)(256 * 65 + 256 * 64) * 4;   // 132096 B
    cudaFuncSetAttribute(k_gemm<128, 128, true>,
                         cudaFuncAttributeMaxDynamicSharedMemorySize, (int)sh1);
    cudaFuncSetAttribute(k_gemm<256, 64, false>,
                         cudaFuncAttributeMaxDynamicSharedMemorySize, (int)sh2);

    const int nbScan = (CN + 1023) / 1024;

    // CSR build
    k_zero_deg<<<(CN + 255) / 256, 256>>>();
    k_count<<<(CE + 255) / 256, 256>>>(ei);
    k_scan_local<<<nbScan, 1024>>>();
    k_scan_bsum<<<1, 32>>>(nbScan);
    k_finalize<<<(CN + 255) / 256, 256>>>();
    k_fill<<<(CE + 255) / 256, 256>>>(ei);

    // weight transposes
    k_wt1<<<(128 * 128 + 255) / 256, 256>>>(W1_l, W1_r);
    k_wt2<<<(256 * 64 + 255) / 256, 256>>>(W2_l, W2_r);

    const int aggBlocks = (CN * 32 + 255) / 256;   // warp per node
    const int gemmGrid  = (CN + 63) / 64;

    // layer 1: mean-aggregate x, then fused GEMM + relu -> h [N,128]
    k_agg64<<<aggBlocks, 256>>>(x, (float*)p_mean1);
    k_gemm<128, 128, true><<<gemmGrid, 256, sh1>>>(
        (const float*)p_mean1, x, (const float*)p_w1t, b1_l, (float*)p_h);

    // layer 2: mean-aggregate h, then fused GEMM -> out [N,64]
    k_agg128<<<aggBlocks, 256>>>((const float*)p_h, (float*)p_mean2);
    k_gemm<256, 64, false><<<gemmGrid, 256, sh2>>>(
        (const float*)p_mean2, (const float*)p_h, (const float*)p_w2t, b2_l, out);
}

// round 7
// speedup vs baseline: 1.6916x; 1.6916x over previous
#include <cuda_runtime.h>
#include <cstdint>

#define CN 100000
#define CE 1600000

// ---------------- device scratch (static, no allocation) ----------------
__device__ int   g_deg[CN];
__device__ int   g_incl[CN];
__device__ int   g_bsum[128];
__device__ int   g_rowptr[CN + 1];
__device__ int   g_wp[CN];
__device__ int   g_col[CE];
__device__ float g_mean1[(size_t)CN * 64];
__device__ float g_h[(size_t)CN * 128];
__device__ float g_pq[(size_t)CN * 128];   // cols 0-63: p = h@W2_l.T, 64-127: q = h@W2_r.T + b2
__device__ float g_W1t[128 * 128];         // [k][o] concat_K(W1_l, W1_r) transposed
__device__ float g_W2t[128 * 128];         // [k][o] concat_O(W2_l, W2_r) transposed
__device__ float g_b2f[128];               // [0..64)=0, [64..128)=b2

// ---------------- CSR construction ----------------
__global__ void k_count(const int* __restrict__ ei) {
    int e = blockIdx.x * blockDim.x + threadIdx.x;
    if (e < CE) atomicAdd(&g_deg[ei[CE + e]], 1);
}

__global__ void k_scan_local() {
    __shared__ int sh[1024];
    int t = threadIdx.x;
    int i = blockIdx.x * 1024 + t;
    int v = (i < CN) ? g_deg[i] : 0;
    sh[t] = v;
    __syncthreads();
    for (int off = 1; off < 1024; off <<= 1) {
        int cur = sh[t];
        int add = (t >= off) ? sh[t - off] : 0;
        __syncthreads();
        sh[t] = cur + add;
        __syncthreads();
    }
    if (i < CN) g_incl[i] = sh[t];
    if (t == 1023) g_bsum[blockIdx.x] = sh[1023];
}

__global__ void k_scan_bsum(int nb) {   // parallel exclusive scan over <=128 block sums
    __shared__ int sh[128];
    int t = threadIdx.x;
    int v = (t < nb) ? g_bsum[t] : 0;
    sh[t] = v;
    __syncthreads();
    for (int off = 1; off < 128; off <<= 1) {
        int cur = sh[t];
        int add = (t >= off) ? sh[t - off] : 0;
        __syncthreads();
        sh[t] = cur + add;
        __syncthreads();
    }
    if (t < nb) g_bsum[t] = sh[t] - v;   // exclusive
}

__global__ void k_finalize() {
    int i = blockIdx.x * blockDim.x + threadIdx.x;
    if (i < CN) {
        int r = g_incl[i] + g_bsum[i >> 10];
        g_rowptr[i + 1] = r;
        g_wp[i] = r - g_deg[i];
        if (i == 0) g_rowptr[0] = 0;
    }
}

__global__ void k_fill(const int* __restrict__ ei) {
    int e = blockIdx.x * blockDim.x + threadIdx.x;
    if (e < CE) {
        int s = ei[e];
        int d = ei[CE + e];
        int p = atomicAdd(&g_wp[d], 1);
        g_col[p] = s;
    }
}

// ---------------- weight prep ----------------
// W1t[k][o] : k<64 -> W1_l[o][k], k>=64 -> W1_r[o][k-64]   (concat over K)
__global__ void k_wt1(const float* __restrict__ Wl, const float* __restrict__ Wr) {
    int idx = blockIdx.x * blockDim.x + threadIdx.x;
    if (idx < 128 * 128) {
        int k = idx >> 7, o = idx & 127;
        g_W1t[idx] = (k < 64) ? Wl[o * 64 + k] : Wr[o * 64 + (k - 64)];
    }
}
// W2t[k][o] : o<64 -> W2_l[o][k], o>=64 -> W2_r[o-64][k]   (concat over O; K=128)
__global__ void k_wt2(const float* __restrict__ Wl, const float* __restrict__ Wr,
                      const float* __restrict__ b2) {
    int idx = blockIdx.x * blockDim.x + threadIdx.x;
    if (idx < 128 * 128) {
        int k = idx >> 7, o = idx & 127;
        g_W2t[idx] = (o < 64) ? Wl[o * 128 + k] : Wr[(o - 64) * 128 + k];
    }
    if (idx < 128) g_b2f[idx] = (idx < 64) ? 0.f : b2[idx - 64];
}

// ---------------- mean aggregation layer1 (warp per node, gather) ----------------
__global__ void k_agg64(const float* __restrict__ feat, float* __restrict__ outm) {
    int w = (blockIdx.x * blockDim.x + threadIdx.x) >> 5;
    int lane = threadIdx.x & 31;
    if (w >= CN) return;
    int s = g_rowptr[w], e = g_rowptr[w + 1];
    float ax = 0.f, ay = 0.f, bx = 0.f, by = 0.f;
    const float2* base = reinterpret_cast<const float2*>(feat);
    int j = s;
    for (; j + 1 < e; j += 2) {
        int c0 = g_col[j];
        int c1 = g_col[j + 1];
        float2 v0 = __ldg(base + (size_t)c0 * 32 + lane);
        float2 v1 = __ldg(base + (size_t)c1 * 32 + lane);
        ax += v0.x; ay += v0.y;
        bx += v1.x; by += v1.y;
    }
    if (j < e) {
        int c0 = g_col[j];
        float2 v0 = __ldg(base + (size_t)c0 * 32 + lane);
        ax += v0.x; ay += v0.y;
    }
    int d = e - s;
    float inv = 1.f / (float)(d > 0 ? d : 1);
    float2 r; r.x = (ax + bx) * inv; r.y = (ay + by) * inv;
    reinterpret_cast<float2*>(outm)[(size_t)w * 32 + lane] = r;
}

// ---------------- final: out = mean_{nbr}(p) + q  (p,q interleaved in g_pq) ----------------
__global__ void k_aggout(float* __restrict__ out) {
    int w = (blockIdx.x * blockDim.x + threadIdx.x) >> 5;
    int lane = threadIdx.x & 31;
    if (w >= CN) return;
    int s = g_rowptr[w], e = g_rowptr[w + 1];
    float ax = 0.f, ay = 0.f, bx = 0.f, by = 0.f;
    const float2* P = reinterpret_cast<const float2*>(g_pq);  // row stride 64 float2
    int j = s;
    for (; j + 1 < e; j += 2) {
        int c0 = g_col[j];
        int c1 = g_col[j + 1];
        float2 v0 = __ldg(P + (size_t)c0 * 64 + lane);
        float2 v1 = __ldg(P + (size_t)c1 * 64 + lane);
        ax += v0.x; ay += v0.y;
        bx += v1.x; by += v1.y;
    }
    if (j < e) {
        int c0 = g_col[j];
        float2 v0 = __ldg(P + (size_t)c0 * 64 + lane);
        ax += v0.x; ay += v0.y;
    }
    int d = e - s;
    float inv = 1.f / (float)(d > 0 ? d : 1);
    float2 q = __ldg(P + (size_t)w * 64 + 32 + lane);  // cols 64..127
    float2 r;
    r.x = q.x + (ax + bx) * inv;
    r.y = q.y + (ay + by) * inv;
    reinterpret_cast<float2*>(out)[(size_t)w * 32 + lane] = r;
}

// ---------------- tensor-core GEMM: out[N,128] = [Aa|As][N,128] @ Wt[128,128] (+bias,(relu)) ----
// 3xTF32 split for ~fp32 accuracy. CTA tile 128x64, warp tile 32x32 (2 m-frags x 4 n-frags).
#define MMA_TF32(D, A, B0, B1)                                              \
    asm volatile(                                                           \
        "mma.sync.aligned.m16n8k8.row.col.f32.tf32.tf32.f32 "               \
        "{%0,%1,%2,%3},{%4,%5,%6,%7},{%8,%9},{%0,%1,%2,%3};"                \
        : "+f"((D)[0]), "+f"((D)[1]), "+f"((D)[2]), "+f"((D)[3])            \
        : "r"((A)[0]), "r"((A)[1]), "r"((A)[2]), "r"((A)[3]),               \
          "r"(B0), "r"(B1))

__device__ __forceinline__ uint32_t f2tf32(float v) {
    uint32_t r;
    asm("cvt.rna.tf32.f32 %0, %1;" : "=r"(r) : "f"(v));
    return r;
}

template <bool RELU>
__global__ __launch_bounds__(256, 2)
void k_mma(const float* __restrict__ Aa, int ldAa,
           const float* __restrict__ As, int ldAs,
           const float* __restrict__ Wt,
           const float* __restrict__ bias,
           float* __restrict__ out) {
    constexpr int ASTR = 36;   // 32 + 4 pad -> conflict-free frag loads
    constexpr int WSTR = 68;   // 64 + 4 pad
    extern __shared__ uint32_t sm[];
    uint32_t* sAh = sm;                       // [128][36]
    uint32_t* sAl = sAh + 128 * ASTR;
    uint32_t* sWh = sAl + 128 * ASTR;         // [32][68]
    uint32_t* sWl = sWh + 32 * WSTR;

    const int tid  = threadIdx.x;
    const int wid  = tid >> 5;
    const int lane = tid & 31;
    const int g    = lane >> 2;     // group row
    const int t    = lane & 3;      // thread-in-group
    const int wy   = wid & 3;       // m-warp (32 rows each)
    const int wx   = wid >> 2;      // n-warp (32 cols each)
    const int m0   = blockIdx.x * 128;
    const int n0   = blockIdx.y * 64;

    float acc[2][4][4];
#pragma unroll
    for (int a = 0; a < 2; a++)
#pragma unroll
        for (int b = 0; b < 4; b++)
#pragma unroll
            for (int c = 0; c < 4; c++) acc[a][b][c] = 0.f;

    for (int s = 0; s < 4; s++) {              // K stages of 32
        if (s) __syncthreads();
        // stage A chunk [128 rows][32 k] with hi/lo split
#pragma unroll
        for (int i = tid; i < 128 * 32; i += 256) {
            int row = i >> 5, kk = i & 31;
            int grow = m0 + row, k = s * 32 + kk;
            float v = 0.f;
            if (grow < CN)
                v = (k < 64) ? __ldg(&Aa[(size_t)grow * ldAa + k])
                             : __ldg(&As[(size_t)grow * ldAs + (k - 64)]);
            uint32_t hb = f2tf32(v);
            float lo = v - __uint_as_float(hb);
            sAh[row * ASTR + kk] = hb;
            sAl[row * ASTR + kk] = f2tf32(lo);
        }
        // stage W chunk [32 k][64 n]
#pragma unroll
        for (int i = tid; i < 32 * 64; i += 256) {
            int kk = i >> 6, n = i & 63;
            float v = __ldg(&Wt[(s * 32 + kk) * 128 + n0 + n]);
            uint32_t hb = f2tf32(v);
            float lo = v - __uint_as_float(hb);
            sWh[kk * WSTR + n] = hb;
            sWl[kk * WSTR + n] = f2tf32(lo);
        }
        __syncthreads();

#pragma unroll
        for (int kc = 0; kc < 4; kc++) {       // k-chunks of 8
            uint32_t ah[2][4], al[2][4];
#pragma unroll
            for (int mf = 0; mf < 2; mf++) {
                int r0 = wy * 32 + mf * 16 + g;
                int c0 = kc * 8 + t;
                ah[mf][0] = sAh[r0 * ASTR + c0];
                ah[mf][1] = sAh[(r0 + 8) * ASTR + c0];
                ah[mf][2] = sAh[r0 * ASTR + c0 + 4];
                ah[mf][3] = sAh[(r0 + 8) * ASTR + c0 + 4];
                al[mf][0] = sAl[r0 * ASTR + c0];
                al[mf][1] = sAl[(r0 + 8) * ASTR + c0];
                al[mf][2] = sAl[r0 * ASTR + c0 + 4];
                al[mf][3] = sAl[(r0 + 8) * ASTR + c0 + 4];
            }
#pragma unroll
            for (int nf = 0; nf < 4; nf++) {
                int nn = wx * 32 + nf * 8 + g;
                int kr = kc * 8 + t;
                uint32_t bh0 = sWh[kr * WSTR + nn];
                uint32_t bh1 = sWh[(kr + 4) * WSTR + nn];
                uint32_t bl0 = sWl[kr * WSTR + nn];
                uint32_t bl1 = sWl[(kr + 4) * WSTR + nn];
#pragma unroll
                for (int mf = 0; mf < 2; mf++) {
                    MMA_TF32(acc[mf][nf], ah[mf], bh0, bh1);   // hi*hi
                    MMA_TF32(acc[mf][nf], al[mf], bh0, bh1);   // lo*hi
                    MMA_TF32(acc[mf][nf], ah[mf], bl0, bl1);   // hi*lo
                }
            }
        }
    }

    // epilogue: bias (+relu), float2 stores (c0,c1 / c2,c3 are adjacent cols)
#pragma unroll
    for (int mf = 0; mf < 2; mf++) {
#pragma unroll
        for (int nf = 0; nf < 4; nf++) {
            int row = m0 + wy * 32 + mf * 16 + g;
            int col = n0 + wx * 32 + nf * 8 + 2 * t;
            float bx = __ldg(&bias[col]);
            float by = __ldg(&bias[col + 1]);
            float2 v;
            if (row < CN) {
                v.x = acc[mf][nf][0] + bx;
                v.y = acc[mf][nf][1] + by;
                if (RELU) { v.x = fmaxf(v.x, 0.f); v.y = fmaxf(v.y, 0.f); }
                *reinterpret_cast<float2*>(&out[(size_t)row * 128 + col]) = v;
            }
            if (row + 8 < CN) {
                v.x = acc[mf][nf][2] + bx;
                v.y = acc[mf][nf][3] + by;
                if (RELU) { v.x = fmaxf(v.x, 0.f); v.y = fmaxf(v.y, 0.f); }
                *reinterpret_cast<float2*>(&out[(size_t)(row + 8) * 128 + col]) = v;
            }
        }
    }
}

// ---------------- host launch ----------------
extern "C" void kernel_launch(void* const* d_in, const int* in_sizes, int n_in,
                              void* d_out, int out_size) {
    const float* x    = (const float*)d_in[0];
    const int*   ei   = (const int*)d_in[1];
    const float* W1_l = (const float*)d_in[2];
    const float* b1_l = (const float*)d_in[3];
    const float* W1_r = (const float*)d_in[4];
    const float* W2_l = (const float*)d_in[5];
    const float* b2_l = (const float*)d_in[6];
    const float* W2_r = (const float*)d_in[7];
    float* out = (float*)d_out;

    void *p_mean1, *p_h, *p_w1t, *p_w2t, *p_b2f, *p_pq, *p_deg;
    cudaGetSymbolAddress(&p_mean1, g_mean1);
    cudaGetSymbolAddress(&p_h, g_h);
    cudaGetSymbolAddress(&p_w1t, g_W1t);
    cudaGetSymbolAddress(&p_w2t, g_W2t);
    cudaGetSymbolAddress(&p_b2f, g_b2f);
    cudaGetSymbolAddress(&p_pq, g_pq);
    cudaGetSymbolAddress(&p_deg, g_deg);

    const int shMMA = (2 * 128 * 36 + 2 * 32 * 68) * 4;   // 54272 B
    cudaFuncSetAttribute(k_mma<true>,
                         cudaFuncAttributeMaxDynamicSharedMemorySize, shMMA);
    cudaFuncSetAttribute(k_mma<false>,
                         cudaFuncAttributeMaxDynamicSharedMemorySize, shMMA);

    const int nbScan = (CN + 1023) / 1024;

    // CSR build
    cudaMemsetAsync(p_deg, 0, CN * sizeof(int));
    k_count<<<(CE + 255) / 256, 256>>>(ei);
    k_scan_local<<<nbScan, 1024>>>();
    k_scan_bsum<<<1, 128>>>(nbScan);
    k_finalize<<<(CN + 255) / 256, 256>>>();
    k_fill<<<(CE + 255) / 256, 256>>>(ei);

    // weight prep
    k_wt1<<<(128 * 128 + 255) / 256, 256>>>(W1_l, W1_r);
    k_wt2<<<(128 * 128 + 255) / 256, 256>>>(W2_l, W2_r, b2_l);

    const int aggBlocks = (CN * 32 + 255) / 256;     // warp per node
    dim3 mmaGrid((CN + 127) / 128, 2);

    // layer 1: aggregate x -> mean1; h = relu([mean1|x] @ W1t + b1)
    k_agg64<<<aggBlocks, 256>>>(x, (float*)p_mean1);
    k_mma<true><<<mmaGrid, 256, shMMA>>>(
        (const float*)p_mean1, 64, x, 64,
        (const float*)p_w1t, b1_l, (float*)p_h);

    // layer 2 (reassociated): [p|q] = h @ W2t (+[0|b2]); out = mean(p_nbr) + q
    k_mma<false><<<mmaGrid, 256, shMMA>>>(
        (const float*)p_h, 128, (const float*)p_h + 64, 128,
        (const float*)p_w2t, (const float*)p_b2f, (float*)p_pq);
    k_aggout<<<aggBlocks, 256>>>(out);
}

// round 8
// speedup vs baseline: 3.1611x; 1.8687x over previous
#include <cuda_runtime.h>
#include <cstdint>

#define CN 100000
#define CE 1600000

// ---------------- device scratch (static, no allocation) ----------------
__device__ int   g_deg[CN];
__device__ int   g_incl[CN];
__device__ int   g_bsum[128];
__device__ int   g_rowptr[CN + 1];
__device__ int   g_wp[CN];
__device__ int   g_col[CE];
__device__ float g_mean1[(size_t)CN * 64];
__device__ float g_h[(size_t)CN * 128];
__device__ float g_pq[(size_t)CN * 128];   // cols 0-63: p = h@W2_l.T, 64-127: q = h@W2_r.T + b2
__device__ float g_W1t[128 * 128];         // [k][o] concat_K(W1_l, W1_r) transposed
__device__ float g_W2t[128 * 128];         // [k][o] concat_O(W2_l, W2_r) transposed
__device__ float g_b2f[128];               // [0..64)=0, [64..128)=b2

// ---------------- CSR construction ----------------
__global__ void k_count(const int* __restrict__ ei) {
    int e4 = blockIdx.x * blockDim.x + threadIdx.x;
    if (e4 * 4 < CE) {
        int4 d = *reinterpret_cast<const int4*>(ei + CE + e4 * 4);
        atomicAdd(&g_deg[d.x], 1);
        atomicAdd(&g_deg[d.y], 1);
        atomicAdd(&g_deg[d.z], 1);
        atomicAdd(&g_deg[d.w], 1);
    }
}

__global__ void k_scan_local() {
    __shared__ int sh[1024];
    int t = threadIdx.x;
    int i = blockIdx.x * 1024 + t;
    int v = (i < CN) ? g_deg[i] : 0;
    sh[t] = v;
    __syncthreads();
    for (int off = 1; off < 1024; off <<= 1) {
        int cur = sh[t];
        int add = (t >= off) ? sh[t - off] : 0;
        __syncthreads();
        sh[t] = cur + add;
        __syncthreads();
    }
    if (i < CN) g_incl[i] = sh[t];
    if (t == 1023) g_bsum[blockIdx.x] = sh[1023];
}

// finalize with fused block-sum scan (each block re-scans <=128 sums in smem)
__global__ void k_finalize(int nb) {
    __shared__ int sb[128];
    int t = threadIdx.x;
    if (t < 128) sb[t] = (t < nb) ? g_bsum[t] : 0;
    __syncthreads();
    for (int off = 1; off < 128; off <<= 1) {
        int cur = (t < 128) ? sb[t] : 0;
        int add = (t >= off && t < 128) ? sb[t - off] : 0;
        __syncthreads();
        if (t < 128) sb[t] = cur + add;   // inclusive
        __syncthreads();
    }
    int i = blockIdx.x * blockDim.x + t;
    if (i < CN) {
        int b = i >> 10;
        int base = (b > 0) ? sb[b - 1] : 0;
        int r = g_incl[i] + base;
        g_rowptr[i + 1] = r;
        g_wp[i] = r - g_deg[i];
        if (i == 0) g_rowptr[0] = 0;
    }
}

__global__ void k_fill(const int* __restrict__ ei) {
    int e4 = blockIdx.x * blockDim.x + threadIdx.x;
    if (e4 * 4 < CE) {
        int4 s = *reinterpret_cast<const int4*>(ei + e4 * 4);
        int4 d = *reinterpret_cast<const int4*>(ei + CE + e4 * 4);
        g_col[atomicAdd(&g_wp[d.x], 1)] = s.x;
        g_col[atomicAdd(&g_wp[d.y], 1)] = s.y;
        g_col[atomicAdd(&g_wp[d.z], 1)] = s.z;
        g_col[atomicAdd(&g_wp[d.w], 1)] = s.w;
    }
}

// ---------------- weight prep (merged) ----------------
// W1t[k][o] : k<64 -> W1_l[o][k], k>=64 -> W1_r[o][k-64]   (concat over K)
// W2t[k][o] : o<64 -> W2_l[o][k], o>=64 -> W2_r[o-64][k]   (concat over O; K=128)
__global__ void k_wt(const float* __restrict__ Wl1, const float* __restrict__ Wr1,
                     const float* __restrict__ Wl2, const float* __restrict__ Wr2,
                     const float* __restrict__ b2) {
    int idx = blockIdx.x * blockDim.x + threadIdx.x;
    if (idx < 128 * 128) {
        int k = idx >> 7, o = idx & 127;
        g_W1t[idx] = (k < 64) ? Wl1[o * 64 + k] : Wr1[o * 64 + (k - 64)];
        g_W2t[idx] = (o < 64) ? Wl2[o * 128 + k] : Wr2[(o - 64) * 128 + k];
    }
    if (idx < 128) g_b2f[idx] = (idx < 64) ? 0.f : b2[idx - 64];
}

// ---------------- mean aggregation layer1 (half-warp per node, float4 gather) ----------------
__global__ void k_agg64(const float* __restrict__ feat, float* __restrict__ outm) {
    int idx = blockIdx.x * blockDim.x + threadIdx.x;
    int node = idx >> 4;
    int l = idx & 15;
    if (node >= CN) return;
    int s = g_rowptr[node], e = g_rowptr[node + 1];
    float ax = 0.f, ay = 0.f, az = 0.f, aw = 0.f;
    float bx = 0.f, by = 0.f, bz = 0.f, bw = 0.f;
    const float4* base = reinterpret_cast<const float4*>(feat);  // row = 16 float4
    int j = s;
    for (; j + 1 < e; j += 2) {
        int c0 = __ldg(&g_col[j]);
        int c1 = __ldg(&g_col[j + 1]);
        float4 v0 = __ldg(base + (size_t)c0 * 16 + l);
        float4 v1 = __ldg(base + (size_t)c1 * 16 + l);
        ax += v0.x; ay += v0.y; az += v0.z; aw += v0.w;
        bx += v1.x; by += v1.y; bz += v1.z; bw += v1.w;
    }
    if (j < e) {
        int c0 = __ldg(&g_col[j]);
        float4 v0 = __ldg(base + (size_t)c0 * 16 + l);
        ax += v0.x; ay += v0.y; az += v0.z; aw += v0.w;
    }
    int d = e - s;
    float inv = 1.f / (float)(d > 0 ? d : 1);
    float4 r;
    r.x = (ax + bx) * inv; r.y = (ay + by) * inv;
    r.z = (az + bz) * inv; r.w = (aw + bw) * inv;
    reinterpret_cast<float4*>(outm)[(size_t)node * 16 + l] = r;
}

// ---------------- final: out = mean_{nbr}(p) + q  (p,q in g_pq rows of 128) ----------------
__global__ void k_aggout(float* __restrict__ out) {
    int idx = blockIdx.x * blockDim.x + threadIdx.x;
    int node = idx >> 4;
    int l = idx & 15;
    if (node >= CN) return;
    int s = g_rowptr[node], e = g_rowptr[node + 1];
    float ax = 0.f, ay = 0.f, az = 0.f, aw = 0.f;
    float bx = 0.f, by = 0.f, bz = 0.f, bw = 0.f;
    const float4* P = reinterpret_cast<const float4*>(g_pq);  // row = 32 float4
    int j = s;
    for (; j + 1 < e; j += 2) {
        int c0 = __ldg(&g_col[j]);
        int c1 = __ldg(&g_col[j + 1]);
        float4 v0 = __ldg(P + (size_t)c0 * 32 + l);
        float4 v1 = __ldg(P + (size_t)c1 * 32 + l);
        ax += v0.x; ay += v0.y; az += v0.z; aw += v0.w;
        bx += v1.x; by += v1.y; bz += v1.z; bw += v1.w;
    }
    if (j < e) {
        int c0 = __ldg(&g_col[j]);
        float4 v0 = __ldg(P + (size_t)c0 * 32 + l);
        ax += v0.x; ay += v0.y; az += v0.z; aw += v0.w;
    }
    int d = e - s;
    float inv = 1.f / (float)(d > 0 ? d : 1);
    float4 q = __ldg(P + (size_t)node * 32 + 16 + l);   // cols 64..127
    float4 r;
    r.x = q.x + (ax + bx) * inv;
    r.y = q.y + (ay + by) * inv;
    r.z = q.z + (az + bz) * inv;
    r.w = q.w + (aw + bw) * inv;
    reinterpret_cast<float4*>(out)[(size_t)node * 16 + l] = r;
}

// ---------------- tensor-core GEMM: out[N,128] = [Aa|As][N,128] @ Wt[128,128] (+bias,(relu)) ----
// 3xTF32 split. CTA tile 128x64, warp tile 32x32. Register-prefetched K stages of 32.
#define MMA_TF32(D, A, B0, B1)                                              \
    asm volatile(                                                           \
        "mma.sync.aligned.m16n8k8.row.col.f32.tf32.tf32.f32 "               \
        "{%0,%1,%2,%3},{%4,%5,%6,%7},{%8,%9},{%0,%1,%2,%3};"                \
        : "+f"((D)[0]), "+f"((D)[1]), "+f"((D)[2]), "+f"((D)[3])            \
        : "r"((A)[0]), "r"((A)[1]), "r"((A)[2]), "r"((A)[3]),               \
          "r"(B0), "r"(B1))

__device__ __forceinline__ uint32_t f2tf32(float v) {
    uint32_t r;
    asm("cvt.rna.tf32.f32 %0, %1;" : "=r"(r) : "f"(v));
    return r;
}

template <bool RELU>
__global__ __launch_bounds__(256, 2)
void k_mma(const float* __restrict__ Aa, int ldAa,
           const float* __restrict__ As, int ldAs,
           const float* __restrict__ Wt,
           const float* __restrict__ bias,
           float* __restrict__ out) {
    constexpr int ASTR = 36;   // %32==4 -> A frag banks 4g+t, unique
    constexpr int WSTR = 72;   // %32==8 -> B frag banks 8t+g, unique (68 had 2-way conflicts)
    extern __shared__ uint32_t sm[];
    uint32_t* sAh = sm;                        // [128][36]
    uint32_t* sAl = sAh + 128 * ASTR;
    uint32_t* sWh = sAl + 128 * ASTR;          // [32][72]
    uint32_t* sWl = sWh + 32 * WSTR;

    const int tid  = threadIdx.x;
    const int wid  = tid >> 5;
    const int lane = tid & 31;
    const int g    = lane >> 2;
    const int t    = lane & 3;
    const int wy   = wid & 3;       // m-warp (32 rows)
    const int wx   = wid >> 2;      // n-warp (32 cols)
    const int m0   = blockIdx.x * 128;
    const int n0   = blockIdx.y * 64;

    float4 aReg[4];                 // prefetch regs: A 16 floats, W 8 floats
    float4 wReg[2];

    float acc[2][4][4];
#pragma unroll
    for (int a = 0; a < 2; a++)
#pragma unroll
        for (int b = 0; b < 4; b++)
#pragma unroll
            for (int c = 0; c < 4; c++) acc[a][b][c] = 0.f;

    auto loadStage = [&](int s) {
        const float* src = (s < 2) ? (Aa + s * 32) : (As + (s - 2) * 32);
        const int ld = (s < 2) ? ldAa : ldAs;
#pragma unroll
        for (int q = 0; q < 4; q++) {
            int idx = tid + q * 256;          // over 1024 float4 = 128 rows x 8
            int row = idx >> 3, kv = idx & 7;
            int grow = m0 + row;
            aReg[q] = (grow < CN)
                ? *reinterpret_cast<const float4*>(src + (size_t)grow * ld + kv * 4)
                : make_float4(0.f, 0.f, 0.f, 0.f);
        }
#pragma unroll
        for (int q = 0; q < 2; q++) {
            int idx = tid + q * 256;          // over 512 float4 = 32 k x 16
            int kk = idx >> 4, nv = idx & 15;
            wReg[q] = *reinterpret_cast<const float4*>(
                Wt + (size_t)(s * 32 + kk) * 128 + n0 + nv * 4);
        }
    };

    auto storeStage = [&]() {
#pragma unroll
        for (int q = 0; q < 4; q++) {
            int idx = tid + q * 256;
            int row = idx >> 3, kk4 = (idx & 7) * 4;
            float4 v = aReg[q];
            uint32_t h0 = f2tf32(v.x), h1 = f2tf32(v.y);
            uint32_t h2 = f2tf32(v.z), h3 = f2tf32(v.w);
            uint4 hh = {h0, h1, h2, h3};
            uint4 ll = {f2tf32(v.x - __uint_as_float(h0)),
                        f2tf32(v.y - __uint_as_float(h1)),
                        f2tf32(v.z - __uint_as_float(h2)),
                        f2tf32(v.w - __uint_as_float(h3))};
            *reinterpret_cast<uint4*>(&sAh[row * ASTR + kk4]) = hh;
            *reinterpret_cast<uint4*>(&sAl[row * ASTR + kk4]) = ll;
        }
#pragma unroll
        for (int q = 0; q < 2; q++) {
            int idx = tid + q * 256;
            int kk = idx >> 4, nv4 = (idx & 15) * 4;
            float4 v = wReg[q];
            uint32_t h0 = f2tf32(v.x), h1 = f2tf32(v.y);
            uint32_t h2 = f2tf32(v.z), h3 = f2tf32(v.w);
            uint4 hh = {h0, h1, h2, h3};
            uint4 ll = {f2tf32(v.x - __uint_as_float(h0)),
                        f2tf32(v.y - __uint_as_float(h1)),
                        f2tf32(v.z - __uint_as_float(h2)),
                        f2tf32(v.w - __uint_as_float(h3))};
            *reinterpret_cast<uint4*>(&sWh[kk * WSTR + nv4]) = hh;
            *reinterpret_cast<uint4*>(&sWl[kk * WSTR + nv4]) = ll;
        }
    };

    loadStage(0);
#pragma unroll
    for (int s = 0; s < 4; s++) {
        if (s) __syncthreads();              // previous compute done reading smem
        storeStage();
        __syncthreads();
        if (s < 3) loadStage(s + 1);         // prefetch next stage behind compute

#pragma unroll
        for (int kc = 0; kc < 4; kc++) {
            uint32_t ah[2][4], al[2][4];
#pragma unroll
            for (int mf = 0; mf < 2; mf++) {
                int r0 = wy * 32 + mf * 16 + g;
                int c0 = kc * 8 + t;
                ah[mf][0] = sAh[r0 * ASTR + c0];
                ah[mf][1] = sAh[(r0 + 8) * ASTR + c0];
                ah[mf][2] = sAh[r0 * ASTR + c0 + 4];
                ah[mf][3] = sAh[(r0 + 8) * ASTR + c0 + 4];
                al[mf][0] = sAl[r0 * ASTR + c0];
                al[mf][1] = sAl[(r0 + 8) * ASTR + c0];
                al[mf][2] = sAl[r0 * ASTR + c0 + 4];
                al[mf][3] = sAl[(r0 + 8) * ASTR + c0 + 4];
            }
#pragma unroll
            for (int nf = 0; nf < 4; nf++) {
                int nn = wx * 32 + nf * 8 + g;
                int kr = kc * 8 + t;
                uint32_t bh0 = sWh[kr * WSTR + nn];
                uint32_t bh1 = sWh[(kr + 4) * WSTR + nn];
                uint32_t bl0 = sWl[kr * WSTR + nn];
                uint32_t bl1 = sWl[(kr + 4) * WSTR + nn];
#pragma unroll
                for (int mf = 0; mf < 2; mf++) {
                    MMA_TF32(acc[mf][nf], ah[mf], bh0, bh1);   // hi*hi
                    MMA_TF32(acc[mf][nf], al[mf], bh0, bh1);   // lo*hi
                    MMA_TF32(acc[mf][nf], ah[mf], bl0, bl1);   // hi*lo
                }
            }
        }
    }

    // epilogue: bias (+relu), float2 stores
#pragma unroll
    for (int mf = 0; mf < 2; mf++) {
#pragma unroll
        for (int nf = 0; nf < 4; nf++) {
            int row = m0 + wy * 32 + mf * 16 + g;
            int col = n0 + wx * 32 + nf * 8 + 2 * t;
            float bx = __ldg(&bias[col]);
            float by = __ldg(&bias[col + 1]);
            float2 v;
            if (row < CN) {
                v.x = acc[mf][nf][0] + bx;
                v.y = acc[mf][nf][1] + by;
                if (RELU) { v.x = fmaxf(v.x, 0.f); v.y = fmaxf(v.y, 0.f); }
                *reinterpret_cast<float2*>(&out[(size_t)row * 128 + col]) = v;
            }
            if (row + 8 < CN) {
                v.x = acc[mf][nf][2] + bx;
                v.y = acc[mf][nf][3] + by;
                if (RELU) { v.x = fmaxf(v.x, 0.f); v.y = fmaxf(v.y, 0.f); }
                *reinterpret_cast<float2*>(&out[(size_t)(row + 8) * 128 + col]) = v;
            }
        }
    }
}

// ---------------- host launch ----------------
extern "C" void kernel_launch(void* const* d_in, const int* in_sizes, int n_in,
                              void* d_out, int out_size) {
    const float* x    = (const float*)d_in[0];
    const int*   ei   = (const int*)d_in[1];
    const float* W1_l = (const float*)d_in[2];
    const float* b1_l = (const float*)d_in[3];
    const float* W1_r = (const float*)d_in[4];
    const float* W2_l = (const float*)d_in[5];
    const float* b2_l = (const float*)d_in[6];
    const float* W2_r = (const float*)d_in[7];
    float* out = (float*)d_out;

    void *p_mean1, *p_h, *p_w1t, *p_w2t, *p_b2f, *p_pq, *p_deg;
    cudaGetSymbolAddress(&p_mean1, g_mean1);
    cudaGetSymbolAddress(&p_h, g_h);
    cudaGetSymbolAddress(&p_w1t, g_W1t);
    cudaGetSymbolAddress(&p_w2t, g_W2t);
    cudaGetSymbolAddress(&p_b2f, g_b2f);
    cudaGetSymbolAddress(&p_pq, g_pq);
    cudaGetSymbolAddress(&p_deg, g_deg);

    const int shMMA = (2 * 128 * 36 + 2 * 32 * 72) * 4;   // 55296 B
    cudaFuncSetAttribute(k_mma<true>,
                         cudaFuncAttributeMaxDynamicSharedMemorySize, shMMA);
    cudaFuncSetAttribute(k_mma<false>,
                         cudaFuncAttributeMaxDynamicSharedMemorySize, shMMA);

    const int nbScan = (CN + 1023) / 1024;

    // CSR build
    cudaMemsetAsync(p_deg, 0, CN * sizeof(int));
    k_count<<<(CE / 4 + 255) / 256, 256>>>(ei);
    k_scan_local<<<nbScan, 1024>>>();
    k_finalize<<<(CN + 255) / 256, 256>>>(nbScan);
    k_fill<<<(CE / 4 + 255) / 256, 256>>>(ei);

    // weight prep
    k_wt<<<(128 * 128 + 255) / 256, 256>>>(W1_l, W1_r, W2_l, W2_r, b2_l);

    const int aggBlocks = (CN * 16 + 255) / 256;     // half-warp per node
    dim3 mmaGrid((CN + 127) / 128, 2);

    // layer 1: aggregate x -> mean1; h = relu([mean1|x] @ W1t + b1)
    k_agg64<<<aggBlocks, 256>>>(x, (float*)p_mean1);
    k_mma<true><<<mmaGrid, 256, shMMA>>>(
        (const float*)p_mean1, 64, x, 64,
        (const float*)p_w1t, b1_l, (float*)p_h);

    // layer 2 (reassociated): [p|q] = h @ W2t (+[0|b2]); out = mean(p_nbr) + q
    k_mma<false><<<mmaGrid, 256, shMMA>>>(
        (const float*)p_h, 128, (const float*)p_h + 64, 128,
        (const float*)p_w2t, (const float*)p_b2f, (float*)p_pq);
    k_aggout<<<aggBlocks, 256>>>(out);
}